// round 3
// baseline (speedup 1.0000x reference)
#include <cuda_runtime.h>
#include <cuda_bf16.h>

#define N_NODES 100000
#define N_EDGES 1600000
#define IN_F    128
#define HID_F   128
#define OUT_F   64

// ---------------- scratch (device globals; no allocation allowed) ----------------
__device__ float g_h[(size_t)N_NODES * HID_F];   // GEMM output per layer
__device__ float g_x[(size_t)N_NODES * HID_F];   // layer activations (ping-pong)
__device__ float g_dsrc[N_NODES];
__device__ float g_ddst[N_NODES];
__device__ int   g_degs[N_NODES];
__device__ int   g_degd[N_NODES];
__device__ int   g_rowoff[N_NODES + 1];
__device__ int   g_ctr[N_NODES];
__device__ int   g_col[N_EDGES];

// ---------------- setup kernels ----------------
__global__ void zero_kernel() {
    int i = blockIdx.x * blockDim.x + threadIdx.x;
    if (i < N_NODES) { g_degs[i] = 0; g_degd[i] = 0; g_ctr[i] = 0; }
}

__global__ void degree_kernel(const int* __restrict__ src, const int* __restrict__ dst) {
    int e = blockIdx.x * blockDim.x + threadIdx.x;
    if (e < N_EDGES) {
        atomicAdd(&g_degs[src[e]], 1);
        atomicAdd(&g_degd[dst[e]], 1);
    }
}

__global__ void inv_kernel() {
    int n = blockIdx.x * blockDim.x + threadIdx.x;
    if (n < N_NODES) {
        g_dsrc[n] = rsqrtf(fmaxf((float)g_degs[n], 1.0f));
        g_ddst[n] = rsqrtf(fmaxf((float)g_degd[n], 1.0f));
    }
}

// Single-block exclusive scan of g_degd -> g_rowoff (100001 entries).
__global__ void scan_kernel() {
    __shared__ int sh[1024];
    const int t = threadIdx.x;
    const int CHUNK = (N_NODES + 1023) / 1024;   // 98
    int start = t * CHUNK;
    int stop  = min(start + CHUNK, N_NODES);
    int s = 0;
    for (int i = start; i < stop; i++) s += g_degd[i];
    sh[t] = s;
    __syncthreads();
    // Hillis-Steele inclusive scan
    for (int off = 1; off < 1024; off <<= 1) {
        int v = (t >= off) ? sh[t - off] : 0;
        __syncthreads();
        sh[t] += v;
        __syncthreads();
    }
    int run = sh[t] - s;   // exclusive prefix for this thread's chunk
    for (int i = start; i < stop; i++) { g_rowoff[i] = run; run += g_degd[i]; }
    if (t == 0) g_rowoff[N_NODES] = sh[1023];
}

__global__ void fill_kernel(const int* __restrict__ src, const int* __restrict__ dst) {
    int e = blockIdx.x * blockDim.x + threadIdx.x;
    if (e < N_EDGES) {
        int d = dst[e];
        int p = g_rowoff[d] + atomicAdd(&g_ctr[d], 1);
        g_col[p] = src[e];
    }
}

// ---------------- GEMM:  C[M,BN] = (A[M,128] * g_dsrc[row]) @ B[128,BN] ----------------
// BM=128, BK=8, TM=8; 256 threads; grid = (1, ceil(M/128)). B width == BN (grid.x==1).
template <int BN, int TN>
__global__ void gemm_scaled_kernel(const float* __restrict__ A,
                                   const float* __restrict__ B,
                                   float* __restrict__ C) {
    constexpr int BM = 128, BK = 8, TM = 8, K = 128;
    constexpr int TCOLS = BN / TN;   // 16 for both configs
    __shared__ float As[BK][BM];
    __shared__ float Bs[BK][BN];

    const int tid  = threadIdx.x;
    const int brow = blockIdx.y * BM;
    const int tcol = (tid % TCOLS) * TN;
    const int trow = (tid / TCOLS) * TM;

    float acc[TM][TN];
#pragma unroll
    for (int i = 0; i < TM; i++)
#pragma unroll
        for (int j = 0; j < TN; j++) acc[i][j] = 0.0f;

    // A-tile load mapping: 128 rows x 8 k, float4 per thread
    const int a_m = tid >> 1;
    const int a_k = (tid & 1) * 4;
    const int grow = brow + a_m;
    const bool avalid = (grow < N_NODES);
    const float sc = avalid ? g_dsrc[grow] : 0.0f;

    for (int k0 = 0; k0 < K; k0 += BK) {
        float4 av = make_float4(0.f, 0.f, 0.f, 0.f);
        if (avalid) av = *(const float4*)(A + (size_t)grow * K + k0 + a_k);
        As[a_k + 0][a_m] = av.x * sc;
        As[a_k + 1][a_m] = av.y * sc;
        As[a_k + 2][a_m] = av.z * sc;
        As[a_k + 3][a_m] = av.w * sc;

        for (int i = tid; i < (BK * BN) / 4; i += 256) {
            int bk = i / (BN / 4);
            int bc = (i % (BN / 4)) * 4;
            float4 bv = *(const float4*)(B + (size_t)(k0 + bk) * BN + bc);
            *(float4*)&Bs[bk][bc] = bv;
        }
        __syncthreads();

#pragma unroll
        for (int kk = 0; kk < BK; kk++) {
            float areg[TM], breg[TN];
#pragma unroll
            for (int i = 0; i < TM; i++) areg[i] = As[kk][trow + i];
#pragma unroll
            for (int j = 0; j < TN; j++) breg[j] = Bs[kk][tcol + j];
#pragma unroll
            for (int i = 0; i < TM; i++)
#pragma unroll
                for (int j = 0; j < TN; j++) acc[i][j] += areg[i] * breg[j];
        }
        __syncthreads();
    }

#pragma unroll
    for (int i = 0; i < TM; i++) {
        int r = brow + trow + i;
        if (r < N_NODES) {
#pragma unroll
            for (int j = 0; j < TN; j += 4) {
                float4 v = make_float4(acc[i][j], acc[i][j + 1], acc[i][j + 2], acc[i][j + 3]);
                *(float4*)(C + (size_t)r * BN + tcol + j) = v;
            }
        }
    }
}

// ---------------- Aggregation: out[n] = act( ddst[n] * sum_{e in CSR(n)} h[col[e]] + b ) ----
// One warp per node; F/32 accumulators per lane.
template <int F, bool RELU>
__global__ void agg_kernel(const float* __restrict__ h,
                           const float* __restrict__ bias,
                           float* __restrict__ out) {
    const int warp = (blockIdx.x * blockDim.x + threadIdx.x) >> 5;
    const int lane = threadIdx.x & 31;
    if (warp >= N_NODES) return;

    const int beg = g_rowoff[warp];
    const int end = g_rowoff[warp + 1];
    constexpr int R = F / 32;
    float acc[R];
#pragma unroll
    for (int r = 0; r < R; r++) acc[r] = 0.0f;

    int i = beg;
    for (; i + 4 <= end; i += 4) {
        int s0 = g_col[i + 0], s1 = g_col[i + 1], s2 = g_col[i + 2], s3 = g_col[i + 3];
        const float* p0 = h + (size_t)s0 * F;
        const float* p1 = h + (size_t)s1 * F;
        const float* p2 = h + (size_t)s2 * F;
        const float* p3 = h + (size_t)s3 * F;
#pragma unroll
        for (int r = 0; r < R; r++) {
            int o = lane + 32 * r;
            acc[r] += (p0[o] + p1[o]) + (p2[o] + p3[o]);
        }
    }
    for (; i < end; i++) {
        const float* p = h + (size_t)g_col[i] * F;
#pragma unroll
        for (int r = 0; r < R; r++) acc[r] += p[lane + 32 * r];
    }

    const float dn = g_ddst[warp];
#pragma unroll
    for (int r = 0; r < R; r++) {
        int o = lane + 32 * r;
        float v = acc[r] * dn + bias[o];
        if (RELU) v = fmaxf(v, 0.0f);
        out[(size_t)warp * F + o] = v;
    }
}

// ---------------- launch ----------------
extern "C" void kernel_launch(void* const* d_in, const int* in_sizes, int n_in,
                              void* d_out, int out_size) {
    const float* features = (const float*)d_in[0];
    const int*   src      = (const int*)d_in[1];
    const int*   dst      = (const int*)d_in[2];
    const float* W1 = (const float*)d_in[3];
    const float* b1 = (const float*)d_in[4];
    const float* W2 = (const float*)d_in[5];
    const float* b2 = (const float*)d_in[6];
    const float* W3 = (const float*)d_in[7];
    const float* b3 = (const float*)d_in[8];
    float* out = (float*)d_out;

    (void)in_sizes; (void)n_in; (void)out_size;

    // Graph structure (rebuilt every call — deterministic work)
    zero_kernel<<<(N_NODES + 255) / 256, 256>>>();
    degree_kernel<<<(N_EDGES + 255) / 256, 256>>>(src, dst);
    inv_kernel<<<(N_NODES + 255) / 256, 256>>>();
    scan_kernel<<<1, 1024>>>();
    fill_kernel<<<(N_EDGES + 255) / 256, 256>>>(src, dst);

    dim3 gblk(256);
    dim3 ggrid128(1, (N_NODES + 127) / 128);
    dim3 ablk(256);
    dim3 agrid((N_NODES + 7) / 8);   // 8 warps/block, 1 warp/node

    // Layer 1: h = (x*dsrc)@W1 ; x = relu(agg*ddst + b1)
    gemm_scaled_kernel<128, 8><<<ggrid128, gblk>>>(features, W1, g_h);
    agg_kernel<128, true><<<agrid, ablk>>>(g_h, b1, g_x);

    // Layer 2
    gemm_scaled_kernel<128, 8><<<ggrid128, gblk>>>(g_x, W2, g_h);
    agg_kernel<128, true><<<agrid, ablk>>>(g_h, b2, g_x);

    // Layer 3 (128 -> 64, no relu)
    gemm_scaled_kernel<64, 4><<<ggrid128, gblk>>>(g_x, W3, g_h);
    agg_kernel<64, false><<<agrid, ablk>>>(g_h, b3, out);
}

// round 5
// speedup vs baseline: 1.1771x; 1.1771x over previous
#include <cuda_runtime.h>
#include <cuda_bf16.h>

#define N_NODES 100000
#define N_EDGES 1600000
#define IN_F    128
#define HID_F   128
#define OUT_F   64

// ---------------- scratch (device globals; no allocation allowed) ----------------
__device__ float g_h[(size_t)N_NODES * HID_F];   // GEMM output per layer
__device__ float g_x[(size_t)N_NODES * HID_F];   // layer activations (ping-pong)
__device__ float g_dsrc[N_NODES];
__device__ float g_ddst[N_NODES];
__device__ int   g_degs[N_NODES];
__device__ int   g_degd[N_NODES];
__device__ int   g_rowoff[N_NODES + 1];
__device__ int   g_ctr[N_NODES];
__device__ int   g_col[N_EDGES];
__device__ int   g_bsum[128];

// ================= setup =================
__global__ void zero_kernel() {
    int i = blockIdx.x * blockDim.x + threadIdx.x;
    if (i < N_NODES) { g_degs[i] = 0; g_degd[i] = 0; g_ctr[i] = 0; }
}

__global__ void degree_kernel(const int* __restrict__ src, const int* __restrict__ dst) {
    int e = blockIdx.x * blockDim.x + threadIdx.x;
    if (e < N_EDGES) {
        atomicAdd(&g_degs[src[e]], 1);
        atomicAdd(&g_degd[dst[e]], 1);
    }
}

// phase 1: per-block sums of g_degd + fused inverse-sqrt degree norms
__global__ void scan1_kernel() {           // grid 98, block 1024
    __shared__ int sh[1024];
    int t = threadIdx.x;
    int i = blockIdx.x * 1024 + t;
    int d = (i < N_NODES) ? g_degd[i] : 0;
    if (i < N_NODES) {
        g_dsrc[i] = rsqrtf(fmaxf((float)g_degs[i], 1.0f));
        g_ddst[i] = rsqrtf(fmaxf((float)d, 1.0f));
    }
    sh[t] = d;
    __syncthreads();
    for (int off = 512; off > 0; off >>= 1) {
        if (t < off) sh[t] += sh[t + off];
        __syncthreads();
    }
    if (t == 0) g_bsum[blockIdx.x] = sh[0];
}

// phase 2: per-block exclusive scan + global base from block sums
__global__ void scan2_kernel() {           // grid 98, block 1024
    __shared__ int sh[1024];
    __shared__ int bs[128];
    const int b = blockIdx.x, t = threadIdx.x;
    if (t < 98) bs[t] = g_bsum[t];
    __syncthreads();
    int base = 0;
    for (int j = 0; j < b; j++) base += bs[j];

    int i = b * 1024 + t;
    int d = (i < N_NODES) ? g_degd[i] : 0;
    sh[t] = d;
    __syncthreads();
    for (int off = 1; off < 1024; off <<= 1) {
        int v = (t >= off) ? sh[t - off] : 0;
        __syncthreads();
        sh[t] += v;
        __syncthreads();
    }
    int excl = sh[t] - d;
    if (i <= N_NODES) g_rowoff[i] = base + excl;
}

__global__ void fill_kernel(const int* __restrict__ src, const int* __restrict__ dst) {
    int e = blockIdx.x * blockDim.x + threadIdx.x;
    if (e < N_EDGES) {
        int d = dst[e];
        int p = g_rowoff[d] + atomicAdd(&g_ctr[d], 1);
        g_col[p] = src[e];
    }
}

// ================= GEMM: C[M,BN] = (A[M,128] * g_dsrc[row]) @ B[128,BN] =================
// BM=128, BK=8, 256 threads. Conflict-free split-column lane tiling:
// thread computes rows [trow, trow+8) x cols {c0..c0+3} (+ {c0+64..c0+67} if BN=128).
template <int BN>
__global__ void gemm_scaled_kernel(const float* __restrict__ A,
                                   const float* __restrict__ B,
                                   float* __restrict__ C) {
    constexpr int BM = 128, BK = 8, K = 128;
    constexpr int NCH = BN / 64;             // 2 for BN=128, 1 for BN=64
    __shared__ float As[BK][BM];
    __shared__ float Bs[BK][BN];

    const int tid  = threadIdx.x;
    const int brow = blockIdx.x * BM;
    const int trow = (tid >> 4) * 8;         // 16 groups x 8 rows
    const int c0   = (tid & 15) * 4;         // 16 groups x 4 cols (conflict-free LDS.128)

    float acc[8][NCH][4];
#pragma unroll
    for (int i = 0; i < 8; i++)
#pragma unroll
        for (int ch = 0; ch < NCH; ch++)
#pragma unroll
            for (int j = 0; j < 4; j++) acc[i][ch][j] = 0.0f;

    const int a_m = tid >> 1;
    const int a_k = (tid & 1) * 4;
    const int grow = brow + a_m;
    const bool avalid = (grow < N_NODES);
    const float sc = avalid ? g_dsrc[grow] : 0.0f;

    for (int k0 = 0; k0 < K; k0 += BK) {
        float4 av = make_float4(0.f, 0.f, 0.f, 0.f);
        if (avalid) av = *(const float4*)(A + (size_t)grow * K + k0 + a_k);
        As[a_k + 0][a_m] = av.x * sc;
        As[a_k + 1][a_m] = av.y * sc;
        As[a_k + 2][a_m] = av.z * sc;
        As[a_k + 3][a_m] = av.w * sc;

#pragma unroll
        for (int i = tid; i < (BK * BN) / 4; i += 256) {
            int bk = i / (BN / 4);
            int bc = (i % (BN / 4)) * 4;
            *(float4*)&Bs[bk][bc] = *(const float4*)(B + (size_t)(k0 + bk) * BN + bc);
        }
        __syncthreads();

#pragma unroll
        for (int kk = 0; kk < BK; kk++) {
            float4 a0 = *(const float4*)&As[kk][trow];
            float4 a1 = *(const float4*)&As[kk][trow + 4];
            float ar[8] = {a0.x, a0.y, a0.z, a0.w, a1.x, a1.y, a1.z, a1.w};
            float br[NCH][4];
#pragma unroll
            for (int ch = 0; ch < NCH; ch++) {
                float4 bv = *(const float4*)&Bs[kk][c0 + ch * 64];
                br[ch][0] = bv.x; br[ch][1] = bv.y; br[ch][2] = bv.z; br[ch][3] = bv.w;
            }
#pragma unroll
            for (int i = 0; i < 8; i++)
#pragma unroll
                for (int ch = 0; ch < NCH; ch++)
#pragma unroll
                    for (int j = 0; j < 4; j++)
                        acc[i][ch][j] += ar[i] * br[ch][j];
        }
        __syncthreads();
    }

#pragma unroll
    for (int i = 0; i < 8; i++) {
        int r = brow + trow + i;
        if (r < N_NODES) {
#pragma unroll
            for (int ch = 0; ch < NCH; ch++) {
                float4 v = make_float4(acc[i][ch][0], acc[i][ch][1],
                                       acc[i][ch][2], acc[i][ch][3]);
                *(float4*)(C + (size_t)r * BN + c0 + ch * 64) = v;
            }
        }
    }
}

// ================= Aggregation, F=128: warp per node, float4 gathers =================
template <bool RELU>
__global__ void agg128_kernel(const float* __restrict__ h,
                              const float* __restrict__ bias,
                              float* __restrict__ out) {
    const int warp = (blockIdx.x * blockDim.x + threadIdx.x) >> 5;
    const int lane = threadIdx.x & 31;
    if (warp >= N_NODES) return;

    const int beg = g_rowoff[warp];
    const int end = g_rowoff[warp + 1];
    const int o = lane * 4;

    float ax = 0.f, ay = 0.f, az = 0.f, aw = 0.f;
    int i = beg;
    for (; i + 8 <= end; i += 8) {
        float4 v[8];
#pragma unroll
        for (int j = 0; j < 8; j++) {
            int s = __ldg(&g_col[i + j]);
            v[j] = __ldg((const float4*)(h + (size_t)s * 128 + o));
        }
#pragma unroll
        for (int j = 0; j < 8; j++) {
            ax += v[j].x; ay += v[j].y; az += v[j].z; aw += v[j].w;
        }
    }
    for (; i < end; i++) {
        int s = __ldg(&g_col[i]);
        float4 v = __ldg((const float4*)(h + (size_t)s * 128 + o));
        ax += v.x; ay += v.y; az += v.z; aw += v.w;
    }

    const float dn = g_ddst[warp];
    float4 bz = *(const float4*)(bias + o);
    float4 r;
    r.x = ax * dn + bz.x;
    r.y = ay * dn + bz.y;
    r.z = az * dn + bz.z;
    r.w = aw * dn + bz.w;
    if (RELU) {
        r.x = fmaxf(r.x, 0.f); r.y = fmaxf(r.y, 0.f);
        r.z = fmaxf(r.z, 0.f); r.w = fmaxf(r.w, 0.f);
    }
    *(float4*)(out + (size_t)warp * 128 + o) = r;
}

// ================= Aggregation, F=64: two nodes per warp (half-warp each) =================
__global__ void agg64_kernel(const float* __restrict__ h,
                             const float* __restrict__ bias,
                             float* __restrict__ out) {
    const int gwarp = (blockIdx.x * blockDim.x + threadIdx.x) >> 5;
    const int lane  = threadIdx.x & 31;
    const int node  = gwarp * 2 + (lane >> 4);
    if (node >= N_NODES) return;
    const int sub = lane & 15;
    const int o = sub * 4;

    const int beg = g_rowoff[node];
    const int end = g_rowoff[node + 1];

    float ax = 0.f, ay = 0.f, az = 0.f, aw = 0.f;
    int i = beg;
    for (; i + 8 <= end; i += 8) {
        float4 v[8];
#pragma unroll
        for (int j = 0; j < 8; j++) {
            int s = __ldg(&g_col[i + j]);
            v[j] = __ldg((const float4*)(h + (size_t)s * 64 + o));
        }
#pragma unroll
        for (int j = 0; j < 8; j++) {
            ax += v[j].x; ay += v[j].y; az += v[j].z; aw += v[j].w;
        }
    }
    for (; i < end; i++) {
        int s = __ldg(&g_col[i]);
        float4 v = __ldg((const float4*)(h + (size_t)s * 64 + o));
        ax += v.x; ay += v.y; az += v.z; aw += v.w;
    }

    const float dn = g_ddst[node];
    float4 bz = *(const float4*)(bias + o);
    float4 r;
    r.x = ax * dn + bz.x;
    r.y = ay * dn + bz.y;
    r.z = az * dn + bz.z;
    r.w = aw * dn + bz.w;
    *(float4*)(out + (size_t)node * 64 + o) = r;
}

// ================= launch =================
extern "C" void kernel_launch(void* const* d_in, const int* in_sizes, int n_in,
                              void* d_out, int out_size) {
    const float* features = (const float*)d_in[0];
    const int*   src      = (const int*)d_in[1];
    const int*   dst      = (const int*)d_in[2];
    const float* W1 = (const float*)d_in[3];
    const float* b1 = (const float*)d_in[4];
    const float* W2 = (const float*)d_in[5];
    const float* b2 = (const float*)d_in[6];
    const float* W3 = (const float*)d_in[7];
    const float* b3 = (const float*)d_in[8];
    float* out = (float*)d_out;

    (void)in_sizes; (void)n_in; (void)out_size;

    const int SCAN_BLOCKS = (N_NODES + 1023) / 1024;   // 98

    // Graph structure (rebuilt every call — deterministic work)
    zero_kernel<<<(N_NODES + 255) / 256, 256>>>();
    degree_kernel<<<(N_EDGES + 255) / 256, 256>>>(src, dst);
    scan1_kernel<<<SCAN_BLOCKS, 1024>>>();
    scan2_kernel<<<SCAN_BLOCKS, 1024>>>();
    fill_kernel<<<(N_EDGES + 255) / 256, 256>>>(src, dst);

    const int GEMM_GRID = (N_NODES + 127) / 128;       // 782
    const int AGG128_GRID = (N_NODES + 7) / 8;         // warp/node, 8 warps/block
    const int AGG64_GRID  = (N_NODES / 2 + 7) / 8;     // 2 nodes/warp

    // Layer 1
    gemm_scaled_kernel<128><<<GEMM_GRID, 256>>>(features, W1, g_h);
    agg128_kernel<true><<<AGG128_GRID, 256>>>(g_h, b1, g_x);

    // Layer 2
    gemm_scaled_kernel<128><<<GEMM_GRID, 256>>>(g_x, W2, g_h);
    agg128_kernel<true><<<AGG128_GRID, 256>>>(g_h, b2, g_x);

    // Layer 3 (128 -> 64, no relu)
    gemm_scaled_kernel<64><<<GEMM_GRID, 256>>>(g_x, W3, g_h);
    agg64_kernel<<<AGG64_GRID, 256>>>(g_h, b3, out);
}

// round 7
// speedup vs baseline: 1.3152x; 1.1173x over previous
#include <cuda_runtime.h>
#include <cuda_bf16.h>

#define N_NODES 100000
#define N_EDGES 1600000
#define IN_F    128
#define HID_F   128
#define OUT_F   64

// ---------------- scratch (device globals; no allocation allowed) ----------------
__device__ float g_h[(size_t)N_NODES * HID_F];   // GEMM output per layer
__device__ float g_x[(size_t)N_NODES * HID_F];   // layer activations (ping-pong)
__device__ float g_dsrc[N_NODES];
__device__ float g_ddst[N_NODES];
__device__ int   g_degs[N_NODES];
__device__ int   g_degd[N_NODES];
__device__ int   g_rowoff[N_NODES + 1];
__device__ int   g_ctr[N_NODES];
__device__ int   g_col[N_EDGES];
__device__ int   g_bsum[128];

// ================= setup =================
__global__ void zero_kernel() {
    int i = blockIdx.x * blockDim.x + threadIdx.x;
    if (i < N_NODES) { g_degs[i] = 0; g_degd[i] = 0; g_ctr[i] = 0; }
}

// 4 edges per thread via int4 (N_EDGES % 4 == 0)
__global__ void degree_kernel(const int* __restrict__ src, const int* __restrict__ dst) {
    int t = blockIdx.x * blockDim.x + threadIdx.x;
    int e = t * 4;
    if (e < N_EDGES) {
        int4 s4 = *(const int4*)(src + e);
        int4 d4 = *(const int4*)(dst + e);
        atomicAdd(&g_degs[s4.x], 1); atomicAdd(&g_degs[s4.y], 1);
        atomicAdd(&g_degs[s4.z], 1); atomicAdd(&g_degs[s4.w], 1);
        atomicAdd(&g_degd[d4.x], 1); atomicAdd(&g_degd[d4.y], 1);
        atomicAdd(&g_degd[d4.z], 1); atomicAdd(&g_degd[d4.w], 1);
    }
}

__global__ void inv_kernel() {
    int i = blockIdx.x * blockDim.x + threadIdx.x;
    if (i < N_NODES) {
        g_dsrc[i] = rsqrtf(fmaxf((float)g_degs[i], 1.0f));
        g_ddst[i] = rsqrtf(fmaxf((float)g_degd[i], 1.0f));
    }
}

// phase 1: per-block sums of g_degd
__global__ void scan1_kernel() {           // grid 98, block 1024
    __shared__ int sh[1024];
    int t = threadIdx.x;
    int i = blockIdx.x * 1024 + t;
    int d = (i < N_NODES) ? g_degd[i] : 0;
    sh[t] = d;
    __syncthreads();
    for (int off = 512; off > 0; off >>= 1) {
        if (t < off) sh[t] += sh[t + off];
        __syncthreads();
    }
    if (t == 0) g_bsum[blockIdx.x] = sh[0];
}

// phase 2: per-block exclusive scan + global base from block sums
__global__ void scan2_kernel() {           // grid 98, block 1024
    __shared__ int sh[1024];
    __shared__ int bs[128];
    const int b = blockIdx.x, t = threadIdx.x;
    if (t < 98) bs[t] = g_bsum[t];
    __syncthreads();
    int base = 0;
    for (int j = 0; j < b; j++) base += bs[j];

    int i = b * 1024 + t;
    int d = (i < N_NODES) ? g_degd[i] : 0;
    sh[t] = d;
    __syncthreads();
    for (int off = 1; off < 1024; off <<= 1) {
        int v = (t >= off) ? sh[t - off] : 0;
        __syncthreads();
        sh[t] += v;
        __syncthreads();
    }
    int excl = sh[t] - d;
    if (i <= N_NODES) g_rowoff[i] = base + excl;
}

// 4 edges per thread via int4
__global__ void fill_kernel(const int* __restrict__ src, const int* __restrict__ dst) {
    int t = blockIdx.x * blockDim.x + threadIdx.x;
    int e = t * 4;
    if (e < N_EDGES) {
        int4 s4 = *(const int4*)(src + e);
        int4 d4 = *(const int4*)(dst + e);
        int p0 = g_rowoff[d4.x] + atomicAdd(&g_ctr[d4.x], 1);
        g_col[p0] = s4.x;
        int p1 = g_rowoff[d4.y] + atomicAdd(&g_ctr[d4.y], 1);
        g_col[p1] = s4.y;
        int p2 = g_rowoff[d4.z] + atomicAdd(&g_ctr[d4.z], 1);
        g_col[p2] = s4.z;
        int p3 = g_rowoff[d4.w] + atomicAdd(&g_ctr[d4.w], 1);
        g_col[p3] = s4.w;
    }
}

// ================= GEMM: C[M,BN] = (A[M,128] * g_dsrc[row]) @ B[128,BN] =================
// BM=128, BK=16, 256 threads. Conflict-free split-column lane tiling.
template <int BN>
__global__ void __launch_bounds__(256)
gemm_scaled_kernel(const float* __restrict__ A,
                   const float* __restrict__ B,
                   float* __restrict__ C) {
    constexpr int BM = 128, BK = 16, K = 128;
    constexpr int NCH = BN / 64;             // 2 for BN=128, 1 for BN=64
    __shared__ float As[BK][BM];
    __shared__ float Bs[BK][BN];

    const int tid  = threadIdx.x;
    const int brow = blockIdx.x * BM;
    const int trow = (tid >> 4) * 8;         // 16 groups x 8 rows
    const int c0   = (tid & 15) * 4;         // 16 groups x 4 cols (conflict-free LDS.128)

    float acc[8][NCH][4];
#pragma unroll
    for (int i = 0; i < 8; i++)
#pragma unroll
        for (int ch = 0; ch < NCH; ch++)
#pragma unroll
            for (int j = 0; j < 4; j++) acc[i][ch][j] = 0.0f;

    // A-tile load mapping: 128 rows x 16 k, 2 float4 per thread
    const int a_m  = tid >> 1;
    const int a_k0 = (tid & 1) * 8;
    const int grow = brow + a_m;
    const bool avalid = (grow < N_NODES);
    const float sc = avalid ? g_dsrc[grow] : 0.0f;

    for (int k0 = 0; k0 < K; k0 += BK) {
        float4 av0 = make_float4(0.f, 0.f, 0.f, 0.f);
        float4 av1 = make_float4(0.f, 0.f, 0.f, 0.f);
        if (avalid) {
            av0 = *(const float4*)(A + (size_t)grow * K + k0 + a_k0);
            av1 = *(const float4*)(A + (size_t)grow * K + k0 + a_k0 + 4);
        }
        As[a_k0 + 0][a_m] = av0.x * sc;
        As[a_k0 + 1][a_m] = av0.y * sc;
        As[a_k0 + 2][a_m] = av0.z * sc;
        As[a_k0 + 3][a_m] = av0.w * sc;
        As[a_k0 + 4][a_m] = av1.x * sc;
        As[a_k0 + 5][a_m] = av1.y * sc;
        As[a_k0 + 6][a_m] = av1.z * sc;
        As[a_k0 + 7][a_m] = av1.w * sc;

#pragma unroll
        for (int i = tid; i < (BK * BN) / 4; i += 256) {
            int bk = i / (BN / 4);
            int bc = (i % (BN / 4)) * 4;
            *(float4*)&Bs[bk][bc] = *(const float4*)(B + (size_t)(k0 + bk) * BN + bc);
        }
        __syncthreads();

#pragma unroll
        for (int kk = 0; kk < BK; kk++) {
            float4 a0 = *(const float4*)&As[kk][trow];
            float4 a1 = *(const float4*)&As[kk][trow + 4];
            float ar[8] = {a0.x, a0.y, a0.z, a0.w, a1.x, a1.y, a1.z, a1.w};
            float br[NCH][4];
#pragma unroll
            for (int ch = 0; ch < NCH; ch++) {
                float4 bv = *(const float4*)&Bs[kk][c0 + ch * 64];
                br[ch][0] = bv.x; br[ch][1] = bv.y; br[ch][2] = bv.z; br[ch][3] = bv.w;
            }
#pragma unroll
            for (int i = 0; i < 8; i++)
#pragma unroll
                for (int ch = 0; ch < NCH; ch++)
#pragma unroll
                    for (int j = 0; j < 4; j++)
                        acc[i][ch][j] += ar[i] * br[ch][j];
        }
        __syncthreads();
    }

#pragma unroll
    for (int i = 0; i < 8; i++) {
        int r = brow + trow + i;
        if (r < N_NODES) {
#pragma unroll
            for (int ch = 0; ch < NCH; ch++) {
                float4 v = make_float4(acc[i][ch][0], acc[i][ch][1],
                                       acc[i][ch][2], acc[i][ch][3]);
                *(float4*)(C + (size_t)r * BN + c0 + ch * 64) = v;
            }
        }
    }
}

// ================= Aggregation, F=128: warp per node, float4 gathers =================
template <bool RELU>
__global__ void agg128_kernel(const float* __restrict__ h,
                              const float* __restrict__ bias,
                              float* __restrict__ out) {
    const int warp = (blockIdx.x * blockDim.x + threadIdx.x) >> 5;
    const int lane = threadIdx.x & 31;
    if (warp >= N_NODES) return;

    const int beg = g_rowoff[warp];
    const int end = g_rowoff[warp + 1];
    const int o = lane * 4;

    float ax = 0.f, ay = 0.f, az = 0.f, aw = 0.f;
    int i = beg;
    for (; i + 8 <= end; i += 8) {
        float4 v[8];
#pragma unroll
        for (int j = 0; j < 8; j++) {
            int s = __ldg(&g_col[i + j]);
            v[j] = __ldg((const float4*)(h + (size_t)s * 128 + o));
        }
#pragma unroll
        for (int j = 0; j < 8; j++) {
            ax += v[j].x; ay += v[j].y; az += v[j].z; aw += v[j].w;
        }
    }
    for (; i < end; i++) {
        int s = __ldg(&g_col[i]);
        float4 v = __ldg((const float4*)(h + (size_t)s * 128 + o));
        ax += v.x; ay += v.y; az += v.z; aw += v.w;
    }

    const float dn = g_ddst[warp];
    float4 bz = *(const float4*)(bias + o);
    float4 r;
    r.x = ax * dn + bz.x;
    r.y = ay * dn + bz.y;
    r.z = az * dn + bz.z;
    r.w = aw * dn + bz.w;
    if (RELU) {
        r.x = fmaxf(r.x, 0.f); r.y = fmaxf(r.y, 0.f);
        r.z = fmaxf(r.z, 0.f); r.w = fmaxf(r.w, 0.f);
    }
    *(float4*)(out + (size_t)warp * 128 + o) = r;
}

// ================= Aggregation, F=64: two nodes per warp (half-warp each) =================
__global__ void agg64_kernel(const float* __restrict__ h,
                             const float* __restrict__ bias,
                             float* __restrict__ out) {
    const int gwarp = (blockIdx.x * blockDim.x + threadIdx.x) >> 5;
    const int lane  = threadIdx.x & 31;
    const int node  = gwarp * 2 + (lane >> 4);
    if (node >= N_NODES) return;
    const int sub = lane & 15;
    const int o = sub * 4;

    const int beg = g_rowoff[node];
    const int end = g_rowoff[node + 1];

    float ax = 0.f, ay = 0.f, az = 0.f, aw = 0.f;
    int i = beg;
    for (; i + 8 <= end; i += 8) {
        float4 v[8];
#pragma unroll
        for (int j = 0; j < 8; j++) {
            int s = __ldg(&g_col[i + j]);
            v[j] = __ldg((const float4*)(h + (size_t)s * 64 + o));
        }
#pragma unroll
        for (int j = 0; j < 8; j++) {
            ax += v[j].x; ay += v[j].y; az += v[j].z; aw += v[j].w;
        }
    }
    for (; i < end; i++) {
        int s = __ldg(&g_col[i]);
        float4 v = __ldg((const float4*)(h + (size_t)s * 64 + o));
        ax += v.x; ay += v.y; az += v.z; aw += v.w;
    }

    const float dn = g_ddst[node];
    float4 bz = *(const float4*)(bias + o);
    float4 r;
    r.x = ax * dn + bz.x;
    r.y = ay * dn + bz.y;
    r.z = az * dn + bz.z;
    r.w = aw * dn + bz.w;
    *(float4*)(out + (size_t)node * 64 + o) = r;
}

// ================= launch =================
extern "C" void kernel_launch(void* const* d_in, const int* in_sizes, int n_in,
                              void* d_out, int out_size) {
    const float* features = (const float*)d_in[0];
    const int*   src      = (const int*)d_in[1];
    const int*   dst      = (const int*)d_in[2];
    const float* W1 = (const float*)d_in[3];
    const float* b1 = (const float*)d_in[4];
    const float* W2 = (const float*)d_in[5];
    const float* b2 = (const float*)d_in[6];
    const float* W3 = (const float*)d_in[7];
    const float* b3 = (const float*)d_in[8];
    float* out = (float*)d_out;

    (void)in_sizes; (void)n_in; (void)out_size;

    const int SCAN_BLOCKS = (N_NODES + 1023) / 1024;   // 98
    const int EDGE4_GRID  = (N_EDGES / 4 + 255) / 256; // 4 edges/thread
    const int GEMM_GRID   = (N_NODES + 127) / 128;     // 782
    const int AGG128_GRID = (N_NODES + 7) / 8;         // warp/node, 8 warps/block
    const int AGG64_GRID  = (N_NODES / 2 + 7) / 8;     // 2 nodes/warp

    // --- setup prefix (gemm1 placed 4th so the profiler's fixed capture slot hits it) ---
    zero_kernel<<<(N_NODES + 255) / 256, 256>>>();                       // 1
    degree_kernel<<<EDGE4_GRID, 256>>>(src, dst);                        // 2
    inv_kernel<<<(N_NODES + 255) / 256, 256>>>();                        // 3
    gemm_scaled_kernel<128><<<GEMM_GRID, 256>>>(features, W1, g_h);      // 4  <- profiled
    scan1_kernel<<<SCAN_BLOCKS, 1024>>>();                               // 5
    scan2_kernel<<<SCAN_BLOCKS, 1024>>>();                               // 6
    fill_kernel<<<EDGE4_GRID, 256>>>(src, dst);                          // 7

    // Layer 1 aggregation
    agg128_kernel<true><<<AGG128_GRID, 256>>>(g_h, b1, g_x);             // 8

    // Layer 2
    gemm_scaled_kernel<128><<<GEMM_GRID, 256>>>(g_x, W2, g_h);           // 9
    agg128_kernel<true><<<AGG128_GRID, 256>>>(g_h, b2, g_x);             // 10

    // Layer 3 (128 -> 64, no relu)
    gemm_scaled_kernel<64><<<GEMM_GRID, 256>>>(g_x, W3, g_h);            // 11
    agg64_kernel<<<AGG64_GRID, 256>>>(g_h, b3, out);                     // 12
}